// round 9
// baseline (speedup 1.0000x reference)
#include <cuda_runtime.h>

#define NN 100000
#define EE 1600000
#define FT 128

// Scratch (allocation-free rule: __device__ globals; all 16B-aligned for v4 ops)
__device__ __align__(16) float g_x[(size_t)NN * FT];    // seq @ W^T
__device__ __align__(16) float g_out[(size_t)NN * FT];  // pre-ReLU accumulator
__device__ __align__(16) float g_deg[NN];
__device__ __align__(16) float g_dinv[NN];
__device__ __align__(16) float g_Wt[FT * FT];           // W transposed: Wt[k][o]

// ---------------------------------------------------------------------------
// 1) Transpose W once (tiny: 16K elements)
// ---------------------------------------------------------------------------
__global__ void transpose_w_kernel(const float* __restrict__ W) {
    int idx = blockIdx.x * blockDim.x + threadIdx.x;
    if (idx < FT * FT) {
        int o = idx / FT, k = idx % FT;      // coalesced read of W[o][k]
        g_Wt[k * FT + o] = W[idx];
    }
}

// ---------------------------------------------------------------------------
// 2) deg init to self-loop fill (3.0)
// ---------------------------------------------------------------------------
__global__ void init_deg_kernel() {
    int i = blockIdx.x * blockDim.x + threadIdx.x;
    if (i < NN) g_deg[i] = 3.0f;
}

// ---------------------------------------------------------------------------
// 3) GEMM: x[n][o] = sum_k seq[n][k] * W[o][k]
//    Block: 64 rows x 128 cols, 256 threads, 8x4 register tile per thread.
//    K-chunked (32): 24KB static shared.
// ---------------------------------------------------------------------------
__global__ void __launch_bounds__(256) gemm_kernel(const float* __restrict__ seq) {
    __shared__ __align__(16) float As[64 * 32];    // 8KB  (row-major chunk)
    __shared__ __align__(16) float Ws[32 * FT];    // 16KB (K-major chunk)

    const int tid  = threadIdx.x;
    const int base = blockIdx.x * 64;
    int rows = NN - base; if (rows > 64) rows = 64;

    const int tc = tid & 31;    // 32 col-groups of 4
    const int tr = tid >> 5;    // 8 row-groups of 8 (whole warp shares tr)

    float acc[8][4];
    #pragma unroll
    for (int j = 0; j < 8; j++)
        #pragma unroll
        for (int c = 0; c < 4; c++) acc[j][c] = 0.0f;

    for (int k0 = 0; k0 < FT; k0 += 32) {
        __syncthreads();   // previous chunk's compute done before overwrite
        // A chunk: 64 rows x 32 k = 512 float4, 2 per thread
        #pragma unroll
        for (int i = 0; i < 2; i++) {
            int f = tid + 256 * i;
            int r = f >> 3, c4 = f & 7;
            float4 v = make_float4(0.f, 0.f, 0.f, 0.f);
            if (r < rows)
                v = *(const float4*)(seq + (size_t)(base + r) * FT + k0 + c4 * 4);
            *(float4*)(As + r * 32 + c4 * 4) = v;
        }
        // W chunk: rows k0..k0+31 of g_Wt = 1024 float4, 4 per thread
        #pragma unroll
        for (int i = 0; i < 4; i++) {
            int f = tid + 256 * i;
            ((float4*)Ws)[f] = *(const float4*)(g_Wt + (size_t)k0 * FT + f * 4);
        }
        __syncthreads();

        #pragma unroll
        for (int k = 0; k < 32; k++) {
            float4 wv = *(const float4*)(Ws + k * FT + tc * 4);
            #pragma unroll
            for (int j = 0; j < 8; j++) {
                float a = As[(tr * 8 + j) * 32 + k];   // warp-broadcast LDS
                acc[j][0] += a * wv.x;
                acc[j][1] += a * wv.y;
                acc[j][2] += a * wv.z;
                acc[j][3] += a * wv.w;
            }
        }
    }

    #pragma unroll
    for (int j = 0; j < 8; j++) {
        int r = base + tr * 8 + j;
        if (r < NN) {
            float4 v = make_float4(acc[j][0], acc[j][1], acc[j][2], acc[j][3]);
            *(float4*)(g_x + (size_t)r * FT + tc * 4) = v;
        }
    }
}

// ---------------------------------------------------------------------------
// 4) Degree accumulation over edges: deg[row[e]] += w[e]
//    edge_index is INT32 (JAX x64 disabled downcasts jnp.int64 -> int32).
// ---------------------------------------------------------------------------
__global__ void deg_kernel(const int* __restrict__ ei,
                           const float* __restrict__ w) {
    int e = blockIdx.x * blockDim.x + threadIdx.x;
    if (e < EE) atomicAdd(&g_deg[ei[e]], w[e]);
}

// ---------------------------------------------------------------------------
// 5) dinv = rsqrt(deg); g_out initialized with self-loop term 3*dinv^2 * x
//    (deg >= 3 always, so the deg>0 guard is vacuous)
// ---------------------------------------------------------------------------
__global__ void dinv_self_kernel() {
    int i = blockIdx.x * blockDim.x + threadIdx.x;   // float4 index
    if (i >= NN * (FT / 4)) return;
    int n = i >> 5;                                  // 32 float4 per row
    float di = rsqrtf(g_deg[n]);
    float s  = 3.0f * di * di;
    float4 v = ((const float4*)g_x)[i];
    v.x *= s; v.y *= s; v.z *= s; v.w *= s;
    ((float4*)g_out)[i] = v;
    if ((i & 31) == 0) g_dinv[n] = di;
}

// ---------------------------------------------------------------------------
// 6) Edge aggregation: g_out[row] += dinv[row]*w*dinv[col] * x[col]
//    One warp per edge; scalar atomics to DEVICE-GLOBAL scratch only.
// ---------------------------------------------------------------------------
__global__ void __launch_bounds__(256) agg_kernel(const int* __restrict__ ei,
                                                  const float* __restrict__ w) {
    int gw   = (blockIdx.x * blockDim.x + threadIdx.x) >> 5;   // edge id
    int lane = threadIdx.x & 31;
    if (gw >= EE) return;

    int r = ei[gw];        // row
    int c = ei[EE + gw];   // col
    float nrm = g_dinv[r] * w[gw] * g_dinv[c];

    float4 v = *(const float4*)(g_x + (size_t)c * FT + lane * 4);
    float* p = g_out + (size_t)r * FT + lane * 4;
    atomicAdd(p + 0, v.x * nrm);
    atomicAdd(p + 1, v.y * nrm);
    atomicAdd(p + 2, v.z * nrm);
    atomicAdd(p + 3, v.w * nrm);
}

// ---------------------------------------------------------------------------
// 7) ReLU + copy to d_out (plain vector stores only on harness memory)
// ---------------------------------------------------------------------------
__global__ void relu_copy_kernel(float* __restrict__ out) {
    int i = blockIdx.x * blockDim.x + threadIdx.x;   // float4 index
    if (i >= NN * (FT / 4)) return;
    float4 v = ((const float4*)g_out)[i];
    v.x = fmaxf(v.x, 0.0f); v.y = fmaxf(v.y, 0.0f);
    v.z = fmaxf(v.z, 0.0f); v.w = fmaxf(v.w, 0.0f);
    ((float4*)out)[i] = v;
}

// ---------------------------------------------------------------------------
extern "C" void kernel_launch(void* const* d_in, const int* in_sizes, int n_in,
                              void* d_out, int out_size) {
    // Resolve inputs by element count (robust to metadata ordering):
    //   seq: NN*FT (12.8M f32), edge_weight: EE (1.6M f32),
    //   W: FT*FT (16384 f32), edge_index: 2*EE (3.2M i32)
    const float* seq = nullptr;
    const float* ew  = nullptr;
    const float* W   = nullptr;
    const int*   ei  = nullptr;
    for (int i = 0; i < n_in; i++) {
        if      (in_sizes[i] == NN * FT) seq = (const float*)d_in[i];
        else if (in_sizes[i] == EE)      ew  = (const float*)d_in[i];
        else if (in_sizes[i] == FT * FT) W   = (const float*)d_in[i];
        else if (in_sizes[i] == 2 * EE)  ei  = (const int*)d_in[i];
    }
    float* out = (float*)d_out;

    transpose_w_kernel<<<(FT * FT + 255) / 256, 256>>>(W);
    init_deg_kernel<<<(NN + 255) / 256, 256>>>();
    gemm_kernel<<<(NN + 63) / 64, 256>>>(seq);
    deg_kernel<<<(EE + 255) / 256, 256>>>(ei, ew);
    dinv_self_kernel<<<(NN * (FT / 4) + 255) / 256, 256>>>();
    agg_kernel<<<(EE * 32) / 256, 256>>>(ei, ew);   // 1 warp / edge, exact grid
    relu_copy_kernel<<<(NN * (FT / 4) + 255) / 256, 256>>>(out);
}

// round 10
// speedup vs baseline: 1.7303x; 1.7303x over previous
#include <cuda_runtime.h>

#define NN 100000
#define EE 1600000
#define FT 128

// Scratch (allocation-free rule: __device__ globals; all 16B-aligned for v4 ops)
__device__ __align__(16) float g_xs[(size_t)NN * FT];   // (seq @ W^T) * dinv[row]
__device__ __align__(16) float g_out[(size_t)NN * FT];  // pre-ReLU accumulator
__device__ __align__(16) float g_deg[NN];
__device__ __align__(16) float g_dinv[NN];
__device__ __align__(16) float g_Wt[FT * FT];           // W transposed: Wt[k][o]

// ---------------------------------------------------------------------------
// 1) Transpose W once (tiny: 16K elements)
// ---------------------------------------------------------------------------
__global__ void transpose_w_kernel(const float* __restrict__ W) {
    int idx = blockIdx.x * blockDim.x + threadIdx.x;
    if (idx < FT * FT) {
        int o = idx / FT, k = idx % FT;      // coalesced read of W[o][k]
        g_Wt[k * FT + o] = W[idx];
    }
}

// ---------------------------------------------------------------------------
// 2) deg init to self-loop fill (3.0)
// ---------------------------------------------------------------------------
__global__ void init_deg_kernel() {
    int i = blockIdx.x * blockDim.x + threadIdx.x;
    if (i < NN) g_deg[i] = 3.0f;
}

// ---------------------------------------------------------------------------
// 3) Degree accumulation: deg[row[e]] += w[e]   (edge_index is int32)
// ---------------------------------------------------------------------------
__global__ void deg_kernel(const int* __restrict__ ei,
                           const float* __restrict__ w) {
    int e = blockIdx.x * blockDim.x + threadIdx.x;
    if (e < EE) atomicAdd(&g_deg[ei[e]], w[e]);
}

// ---------------------------------------------------------------------------
// 4) dinv = rsqrt(deg)  (deg >= 3 always, so deg>0 guard is vacuous)
// ---------------------------------------------------------------------------
__global__ void dinv_kernel() {
    int i = blockIdx.x * blockDim.x + threadIdx.x;
    if (i < NN) g_dinv[i] = rsqrtf(g_deg[i]);
}

// ---------------------------------------------------------------------------
// 5) GEMM with fused scaling epilogue:
//      g_xs[n]  = (seq[n] @ W^T) * dinv[n]
//      g_out[n] = 3*dinv[n] * g_xs[n]          (self-loop init of accumulator)
//    Block: 64 rows x 128 cols, 256 threads, 8x4 register tile per thread.
// ---------------------------------------------------------------------------
__global__ void __launch_bounds__(256) gemm_kernel(const float* __restrict__ seq) {
    __shared__ __align__(16) float As[64 * 32];    // 8KB  (row-major chunk)
    __shared__ __align__(16) float Ws[32 * FT];    // 16KB (K-major chunk)

    const int tid  = threadIdx.x;
    const int base = blockIdx.x * 64;
    int rows = NN - base; if (rows > 64) rows = 64;

    const int tc = tid & 31;    // 32 col-groups of 4
    const int tr = tid >> 5;    // 8 row-groups of 8 (whole warp shares tr)

    float acc[8][4];
    #pragma unroll
    for (int j = 0; j < 8; j++)
        #pragma unroll
        for (int c = 0; c < 4; c++) acc[j][c] = 0.0f;

    for (int k0 = 0; k0 < FT; k0 += 32) {
        __syncthreads();   // previous chunk's compute done before overwrite
        // A chunk: 64 rows x 32 k = 512 float4, 2 per thread
        #pragma unroll
        for (int i = 0; i < 2; i++) {
            int f = tid + 256 * i;
            int r = f >> 3, c4 = f & 7;
            float4 v = make_float4(0.f, 0.f, 0.f, 0.f);
            if (r < rows)
                v = *(const float4*)(seq + (size_t)(base + r) * FT + k0 + c4 * 4);
            *(float4*)(As + r * 32 + c4 * 4) = v;
        }
        // W chunk: rows k0..k0+31 of g_Wt = 1024 float4, 4 per thread
        #pragma unroll
        for (int i = 0; i < 4; i++) {
            int f = tid + 256 * i;
            ((float4*)Ws)[f] = *(const float4*)(g_Wt + (size_t)k0 * FT + f * 4);
        }
        __syncthreads();

        #pragma unroll
        for (int k = 0; k < 32; k++) {
            float4 wv = *(const float4*)(Ws + k * FT + tc * 4);
            #pragma unroll
            for (int j = 0; j < 8; j++) {
                float a = As[(tr * 8 + j) * 32 + k];   // warp-broadcast LDS
                acc[j][0] += a * wv.x;
                acc[j][1] += a * wv.y;
                acc[j][2] += a * wv.z;
                acc[j][3] += a * wv.w;
            }
        }
    }

    #pragma unroll
    for (int j = 0; j < 8; j++) {
        int r = base + tr * 8 + j;
        if (r < NN) {
            float di = g_dinv[r];          // warp-broadcast LDG (L2-resident)
            float s3 = 3.0f * di;
            float4 xs = make_float4(acc[j][0] * di, acc[j][1] * di,
                                    acc[j][2] * di, acc[j][3] * di);
            float4 ov = make_float4(xs.x * s3, xs.y * s3, xs.z * s3, xs.w * s3);
            *(float4*)(g_xs  + (size_t)r * FT + tc * 4) = xs;
            *(float4*)(g_out + (size_t)r * FT + tc * 4) = ov;
        }
    }
}

// ---------------------------------------------------------------------------
// 6) Edge aggregation: g_out[row] += (w[e]*dinv[row]) * g_xs[col]
//    (dinv[col] already folded into g_xs). One warp per edge,
//    one red.global.add.v4.f32 per lane (16B vector reduction).
// ---------------------------------------------------------------------------
__global__ void __launch_bounds__(256) agg_kernel(const int* __restrict__ ei,
                                                  const float* __restrict__ w) {
    int gw   = (blockIdx.x * blockDim.x + threadIdx.x) >> 5;   // edge id
    int lane = threadIdx.x & 31;
    if (gw >= EE) return;

    int r = ei[gw];        // row
    int c = ei[EE + gw];   // col
    float s = w[gw] * g_dinv[r];

    float4 v = *(const float4*)(g_xs + (size_t)c * FT + lane * 4);
    float* p = g_out + (size_t)r * FT + lane * 4;
    asm volatile("red.global.add.v4.f32 [%0], {%1, %2, %3, %4};"
                 :: "l"(p),
                    "f"(v.x * s), "f"(v.y * s), "f"(v.z * s), "f"(v.w * s)
                 : "memory");
}

// ---------------------------------------------------------------------------
// 7) ReLU + copy to d_out (plain vector stores only on harness memory)
// ---------------------------------------------------------------------------
__global__ void relu_copy_kernel(float* __restrict__ out) {
    int i = blockIdx.x * blockDim.x + threadIdx.x;   // float4 index
    if (i >= NN * (FT / 4)) return;
    float4 v = ((const float4*)g_out)[i];
    v.x = fmaxf(v.x, 0.0f); v.y = fmaxf(v.y, 0.0f);
    v.z = fmaxf(v.z, 0.0f); v.w = fmaxf(v.w, 0.0f);
    ((float4*)out)[i] = v;
}

// ---------------------------------------------------------------------------
extern "C" void kernel_launch(void* const* d_in, const int* in_sizes, int n_in,
                              void* d_out, int out_size) {
    // Resolve inputs by element count (robust to metadata ordering):
    //   seq: NN*FT (12.8M f32), edge_weight: EE (1.6M f32),
    //   W: FT*FT (16384 f32), edge_index: 2*EE (3.2M i32)
    const float* seq = nullptr;
    const float* ew  = nullptr;
    const float* W   = nullptr;
    const int*   ei  = nullptr;
    for (int i = 0; i < n_in; i++) {
        if      (in_sizes[i] == NN * FT) seq = (const float*)d_in[i];
        else if (in_sizes[i] == EE)      ew  = (const float*)d_in[i];
        else if (in_sizes[i] == FT * FT) W   = (const float*)d_in[i];
        else if (in_sizes[i] == 2 * EE)  ei  = (const int*)d_in[i];
    }
    float* out = (float*)d_out;

    transpose_w_kernel<<<(FT * FT + 255) / 256, 256>>>(W);
    init_deg_kernel<<<(NN + 255) / 256, 256>>>();
    deg_kernel<<<(EE + 255) / 256, 256>>>(ei, ew);
    dinv_kernel<<<(NN + 255) / 256, 256>>>();
    gemm_kernel<<<(NN + 63) / 64, 256>>>(seq);        // epilogue needs dinv
    agg_kernel<<<(EE * 32) / 256, 256>>>(ei, ew);     // 1 warp / edge, exact grid
    relu_copy_kernel<<<(NN * (FT / 4) + 255) / 256, 256>>>(out);
}